// round 5
// baseline (speedup 1.0000x reference)
#include <cuda_runtime.h>

#define B_   4
#define N_   4096
#define K_   512
#define NCH  64                 // children per CTA
#define GRID_X (N_/NCH)         // 64
#define GRID_TOTAL (GRID_X*B_)  // 256
#define NTHR 256                // each thread owns parents k=2*tid, 2*tid+1
#define DEPTH 4
#define EPSF 1e-6f

typedef unsigned long long ull;

__device__ double   g_blkP[GRID_TOTAL];
__device__ double   g_blkC[GRID_TOTAL];
__device__ float    g_blkM[GRID_TOTAL];
__device__ unsigned g_cnt;   // zero-init; atomicInc wrap resets each launch

__device__ __forceinline__ ull pack2(float lo, float hi) {
    ull r; asm("mov.b64 %0, {%1, %2};" : "=l"(r) : "f"(lo), "f"(hi)); return r;
}
__device__ __forceinline__ float2 unpack2(ull v) {
    float2 r; asm("mov.b64 {%0, %1}, %2;" : "=f"(r.x), "=f"(r.y) : "l"(v)); return r;
}
__device__ __forceinline__ ull fma2(ull a, ull b, ull c) {
    ull d; asm("fma.rn.f32x2 %0, %1, %2, %3;" : "=l"(d) : "l"(a), "l"(b), "l"(c)); return d;
}
__device__ __forceinline__ void lds2(unsigned addr, ull& x, ull& y) {
    asm("ld.shared.v2.b64 {%0, %1}, [%2];" : "=l"(x), "=l"(y) : "r"(addr));
}

// symmetric 3x3 inverse of (S + eps*I)
__device__ __forceinline__ void inv3sym(const float* __restrict__ S,
                                        float& i00, float& i01, float& i02,
                                        float& i11, float& i12, float& i22) {
    float s00 = S[0] + EPSF, s01 = S[1], s02 = S[2];
    float s11 = S[4] + EPSF, s12 = S[5];
    float s22 = S[8] + EPSF;
    float c00 = s11 * s22 - s12 * s12;
    float c01 = s02 * s12 - s01 * s22;
    float c02 = s01 * s12 - s02 * s11;
    float c11 = s00 * s22 - s02 * s02;
    float c12 = s01 * s02 - s00 * s12;
    float c22 = s00 * s11 - s01 * s01;
    float det = s00 * c00 + s01 * c01 + s02 * c02;
    float id  = 1.0f / det;
    i00 = c00 * id; i01 = c01 * id; i02 = c02 * id;
    i11 = c11 * id; i12 = c12 * id; i22 = c22 * id;
}

// epilogue: fold 20 per-k sums with parent features -> (Sp, Sc)
__device__ __forceinline__ void fold_parent(const float* __restrict__ SP,
                                            const float* __restrict__ muP,
                                            int b, int k, const float* g,
                                            float& Sp, float& Sc) {
    float i00, i01, i02, i11, i12, i22;
    inv3sym(SP + (size_t)(b * K_ + k) * 9, i00, i01, i02, i11, i12, i22);
    const float* mp = muP + (size_t)(b * K_ + k) * 3;
    float p0 = mp[0], p1 = mp[1], p2 = mp[2];
    float w0 = i00 * p0 + i01 * p1 + i02 * p2;
    float w1 = i01 * p0 + i11 * p1 + i12 * p2;
    float w2 = i02 * p0 + i12 * p1 + i22 * p2;
    float r  = p0 * w0 + p1 * w1 + p2 * w2;
    // Sp = g0*I00+g1*I11+g2*I22 + 2(g3*I01+g4*I02+g5*I12) - 2(g6*w0+g7*w1+g8*w2) + g9*r
    Sp = g[0]*i00 + g[1]*i11 + g[2]*i22
       + 2.f*(g[3]*i01 + g[4]*i02 + g[5]*i12)
       - 2.f*(g[6]*w0 + g[7]*w1 + g[8]*w2)
       + g[9]*r;
    // Sc = g10*p0^2+g11*p1^2+g12*p2^2 + g13*p0p1+g14*p0p2+g15*p1p2 - 2(g16*p0+g17*p1+g18*p2) + g19
    Sc = g[10]*p0*p0 + g[11]*p1*p1 + g[12]*p2*p2
       + g[13]*p0*p1 + g[14]*p0*p2 + g[15]*p1*p2
       - 2.f*(g[16]*p0 + g[17]*p1 + g[18]*p2)
       + g[19];
}

__global__ void __launch_bounds__(NTHR, 3)
loss_kernel(const float* __restrict__ muC, const float* __restrict__ SC,
            const float* __restrict__ muP, const float* __restrict__ SP,
            const float* __restrict__ A,   const float* __restrict__ mask,
            float* __restrict__ out)
{
    // per child n: 20 features (all pre-multiplied by mask[n]), 80B:
    //  f0..f9  (parent-side maha): c0^2,c1^2,c2^2, c0c1,c0c2,c1c2, c0,c1,c2, 1
    //  f10..f19 (child-side maha): J00,J11,J22, 2J01,2J02,2J12, u0,u1,u2, t
    __shared__ float sh[NCH * 20];
    __shared__ float redP[8], redC[8];
    __shared__ float sMask;
    __shared__ int   sLast;

    const int b   = blockIdx.y;
    const int n0  = blockIdx.x * NCH;
    const int tid = threadIdx.x;

    // ---- child features -> shared ----
    if (tid < NCH) {
        int n = n0 + tid;
        float j00, j01, j02, j11, j12, j22;
        inv3sym(SC + (size_t)(b * N_ + n) * 9, j00, j01, j02, j11, j12, j22);
        const float* mc = muC + (size_t)(b * N_ + n) * 3;
        float c0 = mc[0], c1 = mc[1], c2 = mc[2];
        float u0 = j00 * c0 + j01 * c1 + j02 * c2;
        float u1 = j01 * c0 + j11 * c1 + j12 * c2;
        float u2 = j02 * c0 + j12 * c1 + j22 * c2;
        float t  = c0 * u0 + c1 * u1 + c2 * u2;
        float m  = mask[b * N_ + n];
        float* d = &sh[tid * 20];
        d[0]  = m * c0 * c0;  d[1]  = m * c1 * c1;  d[2]  = m * c2 * c2;
        d[3]  = m * c0 * c1;  d[4]  = m * c0 * c2;  d[5]  = m * c1 * c2;
        d[6]  = m * c0;       d[7]  = m * c1;       d[8]  = m * c2;
        d[9]  = m;
        d[10] = m * j00;      d[11] = m * j11;      d[12] = m * j22;
        d[13] = m * 2.f*j01;  d[14] = m * 2.f*j02;  d[15] = m * 2.f*j12;
        d[16] = m * u0;       d[17] = m * u1;       d[18] = m * u2;
        d[19] = m * t;
    }
    __syncthreads();

    // block mask partial (feature f9 = mask)
    if (tid < 32) {
        float m = sh[(2 * tid) * 20 + 9] + sh[(2 * tid + 1) * 20 + 9];
#pragma unroll
        for (int off = 16; off; off >>= 1)
            m += __shfl_down_sync(0xffffffffu, m, off);
        if (tid == 0) sMask = m;
    }

    unsigned sbase = (unsigned)__cvta_generic_to_shared(sh);
    // thread owns k0 = 2*tid, k1 = 2*tid+1 -> one float2 load of A per n
    const float2* Ap = (const float2*)(A + ((size_t)b * N_ + n0) * K_) + tid;

    float2 abuf[DEPTH];
#pragma unroll
    for (int i = 0; i < DEPTH; i++) abuf[i] = Ap[i * (K_ / 2)];
    Ap += DEPTH * (K_ / 2);

    ull acc[20];
#pragma unroll
    for (int i = 0; i < 20; i++) acc[i] = 0ull;

#pragma unroll 4
    for (int n = 0; n < NCH; ++n) {
        float2 av = abuf[n & (DEPTH - 1)];
        if (n < NCH - DEPTH) {
            abuf[n & (DEPTH - 1)] = Ap[0];
            Ap += K_ / 2;
        }
        ull a0 = pack2(av.x, av.x);
        ull a1 = pack2(av.y, av.y);
        unsigned ad = sbase + n * 80;
        ull F0, F1, F2, F3, F4, F5, F6, F7, F8, F9;
        lds2(ad,      F0, F1);
        lds2(ad + 16, F2, F3);
        lds2(ad + 32, F4, F5);
        lds2(ad + 48, F6, F7);
        lds2(ad + 64, F8, F9);

        acc[0] = fma2(a0, F0, acc[0]);
        acc[1] = fma2(a0, F1, acc[1]);
        acc[2] = fma2(a0, F2, acc[2]);
        acc[3] = fma2(a0, F3, acc[3]);
        acc[4] = fma2(a0, F4, acc[4]);
        acc[5] = fma2(a0, F5, acc[5]);
        acc[6] = fma2(a0, F6, acc[6]);
        acc[7] = fma2(a0, F7, acc[7]);
        acc[8] = fma2(a0, F8, acc[8]);
        acc[9] = fma2(a0, F9, acc[9]);
        acc[10] = fma2(a1, F0, acc[10]);
        acc[11] = fma2(a1, F1, acc[11]);
        acc[12] = fma2(a1, F2, acc[12]);
        acc[13] = fma2(a1, F3, acc[13]);
        acc[14] = fma2(a1, F4, acc[14]);
        acc[15] = fma2(a1, F5, acc[15]);
        acc[16] = fma2(a1, F6, acc[16]);
        acc[17] = fma2(a1, F7, acc[17]);
        acc[18] = fma2(a1, F8, acc[18]);
        acc[19] = fma2(a1, F9, acc[19]);
    }

    // ---- epilogue: fold with parent features ----
    float g[20];
#pragma unroll
    for (int i = 0; i < 10; i++) {
        float2 v = unpack2(acc[i]);
        g[2 * i] = v.x;
        g[2 * i + 1] = v.y;
    }
    float Sp0, Sc0;
    fold_parent(SP, muP, b, 2 * tid, g, Sp0, Sc0);
#pragma unroll
    for (int i = 0; i < 10; i++) {
        float2 v = unpack2(acc[10 + i]);
        g[2 * i] = v.x;
        g[2 * i + 1] = v.y;
    }
    float Sp1, Sc1;
    fold_parent(SP, muP, b, 2 * tid + 1, g, Sp1, Sc1);
    float sp = Sp0 + Sp1;
    float sc = Sc0 + Sc1;

    // ---- in-block reduction ----
#pragma unroll
    for (int off = 16; off; off >>= 1) {
        sp += __shfl_down_sync(0xffffffffu, sp, off);
        sc += __shfl_down_sync(0xffffffffu, sc, off);
    }
    int wid = tid >> 5, lane = tid & 31;
    if (lane == 0) { redP[wid] = sp; redC[wid] = sc; }
    __syncthreads();

    const int bid = blockIdx.y * gridDim.x + blockIdx.x;
    if (tid == 0) {
        float tp = 0.f, tc = 0.f;
#pragma unroll
        for (int i = 0; i < 8; i++) { tp += redP[i]; tc += redC[i]; }
        g_blkP[bid] = (double)tp;
        g_blkC[bid] = (double)tc;
        g_blkM[bid] = sMask;
        __threadfence();
        unsigned t = atomicInc(&g_cnt, GRID_TOTAL - 1);
        sLast = (t == GRID_TOTAL - 1);
    }
    __syncthreads();

    // ---- last block: final reduction + output ----
    if (sLast) {
        __threadfence();
        __shared__ double fP[8], fC[8];
        __shared__ float  fM[8];
        double p = g_blkP[tid];   // 256 slots, 256 threads
        double c = g_blkC[tid];
        float  m = g_blkM[tid];
#pragma unroll
        for (int off = 16; off; off >>= 1) {
            p += __shfl_down_sync(0xffffffffu, p, off);
            c += __shfl_down_sync(0xffffffffu, c, off);
            m += __shfl_down_sync(0xffffffffu, m, off);
        }
        if (lane == 0) { fP[wid] = p; fC[wid] = c; fM[wid] = m; }
        __syncthreads();
        if (tid == 0) {
            double tp = 0.0, tc = 0.0;
            float  tm = 0.f;
#pragma unroll
            for (int i = 0; i < 8; i++) { tp += fP[i]; tc += fC[i]; tm += fM[i]; }
            double denom = (tm > 1.f) ? (double)tm : 1.0;
            out[0] = (float)((tp + tc) / denom);  // final_loss
            out[1] = (float)(tp / denom);          // dist_p_m
            out[2] = (float)(tc / denom);          // dist_c_m
        }
    }
}

extern "C" void kernel_launch(void* const* d_in, const int* in_sizes, int n_in,
                              void* d_out, int out_size) {
    const float* muC  = (const float*)d_in[0];
    const float* SC   = (const float*)d_in[1];
    const float* muP  = (const float*)d_in[2];
    const float* SP   = (const float*)d_in[3];
    const float* A    = (const float*)d_in[4];
    const float* mask = (const float*)d_in[5];

    dim3 grid(GRID_X, B_);
    loss_kernel<<<grid, NTHR>>>(muC, SC, muP, SP, A, mask, (float*)d_out);
}

// round 6
// speedup vs baseline: 1.0861x; 1.0861x over previous
#include <cuda_runtime.h>

#define B_   4
#define N_   4096
#define K_   512
#define NT   64
#define NPAIR (NT/2)            // 32
#define GRID_X (N_/NT)          // 64
#define KSPLIT 2
#define GRID_TOTAL (GRID_X*B_*KSPLIT)  // 512
#define NTHR 256                // 1 parent per thread
#define DEPTH 8                 // A prefetch depth (iters), 2 LDG/iter
#define EPSF 1e-6f

typedef unsigned long long ull;

__device__ double   g_blkP[GRID_TOTAL];
__device__ double   g_blkC[GRID_TOTAL];
__device__ float    g_blkM[GRID_TOTAL];
__device__ unsigned g_cnt;   // zero-init; atomicInc wrap resets each launch

__device__ __forceinline__ ull pack2(float lo, float hi) {
    ull r; asm("mov.b64 %0, {%1, %2};" : "=l"(r) : "f"(lo), "f"(hi)); return r;
}
__device__ __forceinline__ float2 unpack2(ull v) {
    float2 r; asm("mov.b64 {%0, %1}, %2;" : "=f"(r.x), "=f"(r.y) : "l"(v)); return r;
}
__device__ __forceinline__ ull fma2(ull a, ull b, ull c) {
    ull d; asm("fma.rn.f32x2 %0, %1, %2, %3;" : "=l"(d) : "l"(a), "l"(b), "l"(c)); return d;
}
__device__ __forceinline__ ull mul2(ull a, ull b) {
    ull d; asm("mul.rn.f32x2 %0, %1, %2;" : "=l"(d) : "l"(a), "l"(b)); return d;
}
__device__ __forceinline__ ull add2(ull a, ull b) {
    ull d; asm("add.rn.f32x2 %0, %1, %2;" : "=l"(d) : "l"(a), "l"(b)); return d;
}
__device__ __forceinline__ void lds2(unsigned addr, ull& x, ull& y) {
    asm("ld.shared.v2.b64 {%0, %1}, [%2];" : "=l"(x), "=l"(y) : "r"(addr));
}

// symmetric 3x3 inverse of (S + eps*I)
__device__ __forceinline__ void inv3sym(const float* __restrict__ S,
                                        float& i00, float& i01, float& i02,
                                        float& i11, float& i12, float& i22) {
    float s00 = S[0] + EPSF, s01 = S[1], s02 = S[2];
    float s11 = S[4] + EPSF, s12 = S[5];
    float s22 = S[8] + EPSF;
    float c00 = s11 * s22 - s12 * s12;
    float c01 = s02 * s12 - s01 * s22;
    float c02 = s01 * s12 - s02 * s11;
    float c11 = s00 * s22 - s02 * s02;
    float c12 = s01 * s02 - s00 * s12;
    float c22 = s00 * s11 - s01 * s01;
    float det = s00 * c00 + s01 * c01 + s02 * c02;
    float id  = 1.0f / det;
    i00 = c00 * id; i01 = c01 * id; i02 = c02 * id;
    i11 = c11 * id; i12 = c12 * id; i22 = c22 * id;
}

__global__ void __launch_bounds__(NTHR, 3)
loss_kernel(const float* __restrict__ muC, const float* __restrict__ SC,
            const float* __restrict__ muP, const float* __restrict__ SP,
            const float* __restrict__ A,   const float* __restrict__ mask,
            float* __restrict__ out)
{
    // per n-pair child features, interleaved {even,odd}:
    // c0,c1,c2, I00,I11,I22, 2*I01,2*I02,2*I12, m  -> 10 x 2 floats = 80B
    __shared__ float sh[NPAIR * 20];
    __shared__ float redP[8], redC[8];
    __shared__ float sMask;
    __shared__ int   sLast;

    const int b   = blockIdx.y;
    const int n0  = blockIdx.x * NT;
    const int tid = threadIdx.x;
    const int k   = blockIdx.z * NTHR + tid;   // 1 parent per thread

    // ---- parent features (9 packed regs) ----
    float i00, i01, i02, i11, i12, i22;
    inv3sym(SP + (size_t)(b * K_ + k) * 9, i00, i01, i02, i11, i12, i22);
    const float* mp = muP + (size_t)(b * K_ + k) * 3;
    float p0 = mp[0], p1 = mp[1], p2 = mp[2];
    ull Pn0  = pack2(-p0, -p0), Pn1 = pack2(-p1, -p1), Pn2 = pack2(-p2, -p2);
    ull PI00 = pack2(i00, i00), PI11 = pack2(i11, i11), PI22 = pack2(i22, i22);
    ull PI01 = pack2(2.f * i01, 2.f * i01);
    ull PI02 = pack2(2.f * i02, 2.f * i02);
    ull PI12 = pack2(2.f * i12, 2.f * i12);

    // ---- child features -> shared (threads 0..NT-1, one child each) ----
    if (tid < NT) {
        int n = n0 + tid;
        float j00, j01, j02, j11, j12, j22;
        inv3sym(SC + (size_t)(b * N_ + n) * 9, j00, j01, j02, j11, j12, j22);
        const float* mc = muC + (size_t)(b * N_ + n) * 3;
        float* d = &sh[(tid >> 1) * 20 + (tid & 1)];
        d[0]  = mc[0];        d[2]  = mc[1];        d[4]  = mc[2];
        d[6]  = j00;          d[8]  = j11;          d[10] = j22;
        d[12] = 2.f * j01;    d[14] = 2.f * j02;    d[16] = 2.f * j12;
        d[18] = mask[b * N_ + n];
    }
    __syncthreads();

    // block mask partial: warp 0, one n-pair per lane (NPAIR=32)
    if (tid < 32) {
        float m = sh[tid * 20 + 18] + sh[tid * 20 + 19];
#pragma unroll
        for (int off = 16; off; off >>= 1)
            m += __shfl_down_sync(0xffffffffu, m, off);
        if (tid == 0) sMask = (blockIdx.z == 0) ? m : 0.f;  // count mask once
    }

    unsigned sbase = (unsigned)__cvta_generic_to_shared(sh);
    const float* Ap = A + ((size_t)b * N_ + n0) * K_ + k;

    // depth-8 prefetch of A (2 loads per iter: {n, n+1})
    float abuf[2 * DEPTH];
#pragma unroll
    for (int i = 0; i < DEPTH; i++) {
        abuf[2 * i]     = Ap[0];
        abuf[2 * i + 1] = Ap[K_];
        Ap += 2 * K_;
    }

    ull accP = 0ull, accC = 0ull;

#pragma unroll 8
    for (int p = 0; p < NPAIR; ++p) {
        int s = (p & (DEPTH - 1)) * 2;
        float a0 = abuf[s], a1 = abuf[s + 1];
        if (p < NPAIR - DEPTH) {
            abuf[s]     = Ap[0];
            abuf[s + 1] = Ap[K_];
            Ap += 2 * K_;
        }
        unsigned ad = sbase + p * 80;
        ull Fc0, Fc1, Fc2, FI00, FI11, FI22, FI01, FI02, FI12, Fm;
        lds2(ad,      Fc0,  Fc1 );
        lds2(ad + 16, Fc2,  FI00);
        lds2(ad + 32, FI11, FI22);
        lds2(ad + 48, FI01, FI02);
        lds2(ad + 64, FI12, Fm  );

        ull d0 = add2(Fc0, Pn0);
        ull d1 = add2(Fc1, Pn1);
        ull d2 = add2(Fc2, Pn2);
        ull dd00 = mul2(d0, d0);
        ull dd11 = mul2(d1, d1);
        ull dd22 = mul2(d2, d2);
        ull dd01 = mul2(d0, d1);
        ull dd02 = mul2(d0, d2);
        ull dd12 = mul2(d1, d2);

        ull mpv = mul2(dd00, PI00);
        mpv = fma2(dd11, PI11, mpv);
        mpv = fma2(dd22, PI22, mpv);
        mpv = fma2(dd01, PI01, mpv);
        mpv = fma2(dd02, PI02, mpv);
        mpv = fma2(dd12, PI12, mpv);

        ull mcv = mul2(dd00, FI00);
        mcv = fma2(dd11, FI11, mcv);
        mcv = fma2(dd22, FI22, mcv);
        mcv = fma2(dd01, FI01, mcv);
        mcv = fma2(dd02, FI02, mcv);
        mcv = fma2(dd12, FI12, mcv);

        ull am = mul2(pack2(a0, a1), Fm);   // A * mask
        accP = fma2(am, mpv, accP);
        accC = fma2(am, mcv, accC);
    }

    // ---- in-block reduction ----
    float2 vP = unpack2(accP), vC = unpack2(accC);
    float sp = vP.x + vP.y;
    float sc = vC.x + vC.y;
#pragma unroll
    for (int off = 16; off; off >>= 1) {
        sp += __shfl_down_sync(0xffffffffu, sp, off);
        sc += __shfl_down_sync(0xffffffffu, sc, off);
    }
    int wid = tid >> 5, lane = tid & 31;
    if (lane == 0) { redP[wid] = sp; redC[wid] = sc; }
    __syncthreads();

    const int bid = (blockIdx.z * B_ + blockIdx.y) * GRID_X + blockIdx.x;
    if (tid == 0) {
        float tp = 0.f, tc = 0.f;
#pragma unroll
        for (int i = 0; i < 8; i++) { tp += redP[i]; tc += redC[i]; }
        g_blkP[bid] = (double)tp;
        g_blkC[bid] = (double)tc;
        g_blkM[bid] = sMask;
        __threadfence();
        unsigned t = atomicInc(&g_cnt, GRID_TOTAL - 1);
        sLast = (t == GRID_TOTAL - 1);
    }
    __syncthreads();

    // ---- last block: final reduction + output ----
    if (sLast) {
        __threadfence();
        __shared__ double fP[8], fC[8];
        __shared__ float  fM[8];
        double p = g_blkP[tid]        + g_blkP[tid + NTHR];   // 512 slots
        double c = g_blkC[tid]        + g_blkC[tid + NTHR];
        float  m = g_blkM[tid]        + g_blkM[tid + NTHR];
#pragma unroll
        for (int off = 16; off; off >>= 1) {
            p += __shfl_down_sync(0xffffffffu, p, off);
            c += __shfl_down_sync(0xffffffffu, c, off);
            m += __shfl_down_sync(0xffffffffu, m, off);
        }
        if (lane == 0) { fP[wid] = p; fC[wid] = c; fM[wid] = m; }
        __syncthreads();
        if (tid == 0) {
            double tp = 0.0, tc = 0.0;
            float  tm = 0.f;
#pragma unroll
            for (int i = 0; i < 8; i++) { tp += fP[i]; tc += fC[i]; tm += fM[i]; }
            double denom = (tm > 1.f) ? (double)tm : 1.0;
            out[0] = (float)((tp + tc) / denom);  // final_loss
            out[1] = (float)(tp / denom);          // dist_p_m
            out[2] = (float)(tc / denom);          // dist_c_m
        }
    }
}

extern "C" void kernel_launch(void* const* d_in, const int* in_sizes, int n_in,
                              void* d_out, int out_size) {
    const float* muC  = (const float*)d_in[0];
    const float* SC   = (const float*)d_in[1];
    const float* muP  = (const float*)d_in[2];
    const float* SP   = (const float*)d_in[3];
    const float* A    = (const float*)d_in[4];
    const float* mask = (const float*)d_in[5];

    dim3 grid(GRID_X, B_, KSPLIT);
    loss_kernel<<<grid, NTHR>>>(muC, SC, muP, SP, A, mask, (float*)d_out);
}